// round 11
// baseline (speedup 1.0000x reference)
#include <cuda_runtime.h>
#include <math.h>

// Problem constants
#define NBATCH   64
#define NCH      128
#define NPTS     256           // 16x16 image grid
#define MAPS     32            // BEV map size
#define NCELLS   (MAPS*MAPS)   // 1024
#define HMAXV    14
#define GROUPS   8             // channel groups per batch (single wave: 512 blocks)
#define CH_PER   (NCH / GROUPS)   // 16

__global__ __launch_bounds__(256)
void voxelize_kernel(const float* __restrict__ features,   // (64,128,256)
                     const float* __restrict__ depth,      // (64,1,256)
                     const float* __restrict__ cam,        // (3,256)
                     float* __restrict__ out)              // (64,128,32,32)
{
    __shared__ __align__(16) int   win[NCELLS];          // packed (y<<8)|tid, -1 empty
    __shared__ __align__(16) float sf [CH_PER * NPTS];   // staged features (16KB)
    __shared__ int duplist[NPTS];                        // packed (cell<<8)|tid
    __shared__ int dupcnt;

    const int tid = threadIdx.x;        // 0..255 == point id
    const int b   = blockIdx.y;         // batch
    const int g   = blockIdx.x;         // channel group
    const int cl4 = tid * 4;            // this thread's 4 cells

    // ---- issue long-latency loads FIRST (depth/cam + feature staging) ----
    const float d  = depth[b * NPTS + tid];
    const float cx = cam[          tid];
    const float cy = cam[  NPTS  + tid];
    const float cz = cam[2*NPTS  + tid];

    const float* __restrict__ fb = features + (size_t)(b * NCH + g * CH_PER) * NPTS;
    {
        const float4* __restrict__ src = reinterpret_cast<const float4*>(fb);
        float4* dst = reinterpret_cast<float4*>(sf);
        #pragma unroll
        for (int i = 0; i < (CH_PER * NPTS / 4) / 256; i++)   // 4 iters
            dst[tid + i * 256] = src[tid + i * 256];
    }

    // ---- init winner table (overlaps load latency) ----
    *reinterpret_cast<int4*>(&win[cl4]) = make_int4(-1, -1, -1, -1);
    if (tid == 0) dupcnt = 0;

    // ---- per-point voxel index math (bit-exact vs JAX float32) ----
    const float px = __fmul_rn(d, cx);
    const float py = __fadd_rn(__fmul_rn(d, cy), 1.72f);   // + CAM_HEIGHT
    const float pz = __fmul_rn(d, cz);

    const float CELLF = 0.1f;  // float32(3.2/32)
    const int xi = (int)floorf(__fdiv_rn(px, CELLF)) + (MAPS / 2);
    const int yi = (int)floorf(__fdiv_rn(py, CELLF));
    const int zi = (int)floorf(__fdiv_rn(pz, CELLF)) + MAPS;

    const bool valid = (xi >= 0) & (xi < MAPS) & (zi >= 0) & (zi < MAPS) & (yi < HMAXV);

    // replicate reference flat index semantics: flat = (z*32+x)*14 + y
    int cell = -1, ye = -1;
    if (valid) {
        const int vflat = (zi * MAPS + xi) * HMAXV + yi;
        if (vflat >= 0) {
            cell = vflat / HMAXV;           // ye in [0,13]
            ye   = vflat - cell * HMAXV;
        }
    }
    __syncthreads();   // b1: win/dupcnt init visible

    // ---- phase 1: packed winner max (y major, tid minor) ----
    if (cell >= 0) atomicMax(&win[cell], (ye << 8) | tid);
    __syncthreads();   // b2: winners final

    // ---- phase 2: losers at the winning voxel register as duplicates (rare) ----
    if (cell >= 0) {
        const int w = win[cell];
        if ((w >> 8) == ye && (w & 255) != tid) {
            const int slot = atomicAdd(&dupcnt, 1);
            duplist[slot] = (cell << 8) | tid;
        }
    }
    __syncthreads();   // b3: duplist final

    // ---- resolve this thread's 4 cells once (channel-invariant) ----
    const int4 w4 = *reinterpret_cast<const int4*>(&win[cl4]);
    const int f0 = (w4.x < 0) ? -1 : (w4.x & 255);
    const int f1 = (w4.y < 0) ? -1 : (w4.y & 255);
    const int f2 = (w4.z < 0) ? -1 : (w4.z & 255);
    const int f3 = (w4.w < 0) ? -1 : (w4.w & 255);

    const int ndup = dupcnt;
    bool hasdup = false;
    for (int k = 0; k < ndup; k++) {
        const int dc = duplist[k] >> 8;
        hasdup |= (dc >= cl4) && (dc < cl4 + 4);
    }

    float* __restrict__ ob = out + (size_t)(b * NCH + g * CH_PER) * NCELLS + cl4;

    if (!hasdup) {
        // common path: predicated smem gathers + coalesced STG.128
        #pragma unroll
        for (int c = 0; c < CH_PER; c++) {
            const float* __restrict__ frow = sf + c * NPTS;
            float4 v = make_float4(0.f, 0.f, 0.f, 0.f);
            if (f0 >= 0) v.x = frow[f0];
            if (f1 >= 0) v.y = frow[f1];
            if (f2 >= 0) v.z = frow[f2];
            if (f3 >= 0) v.w = frow[f3];
            *reinterpret_cast<float4*>(ob + c * NCELLS) = v;
        }
    } else {
        // rare threads owning a duplicated cell: add loser contributions too
        #pragma unroll 4
        for (int c = 0; c < CH_PER; c++) {
            const float* __restrict__ frow = sf + c * NPTS;
            float4 v = make_float4(0.f, 0.f, 0.f, 0.f);
            if (f0 >= 0) v.x = frow[f0];
            if (f1 >= 0) v.y = frow[f1];
            if (f2 >= 0) v.z = frow[f2];
            if (f3 >= 0) v.w = frow[f3];
            for (int k = 0; k < ndup; k++) {
                const int e  = duplist[k];
                const int dc = e >> 8;
                const int dt = e & 255;
                if      (dc == cl4    ) v.x += frow[dt];
                else if (dc == cl4 + 1) v.y += frow[dt];
                else if (dc == cl4 + 2) v.z += frow[dt];
                else if (dc == cl4 + 3) v.w += frow[dt];
            }
            *reinterpret_cast<float4*>(ob + c * NCELLS) = v;
        }
    }
}

extern "C" void kernel_launch(void* const* d_in, const int* in_sizes, int n_in,
                              void* d_out, int out_size)
{
    const float* features = (const float*)d_in[0];   // 64*128*16*16
    const float* depth    = (const float*)d_in[1];   // 64*1*16*16
    const float* cam      = (const float*)d_in[2];   // 3*256
    float*       out      = (float*)d_out;           // 64*128*32*32

    dim3 grid(GROUPS, NBATCH);
    voxelize_kernel<<<grid, 256>>>(features, depth, cam, out);
}

// round 12
// speedup vs baseline: 1.0963x; 1.0963x over previous
#include <cuda_runtime.h>
#include <math.h>

// Problem constants
#define NBATCH   64
#define NCH      128
#define NPTS     256           // 16x16 image grid
#define MAPS     32            // BEV map size
#define NCELLS   (MAPS*MAPS)   // 1024
#define HMAXV    14
#define GROUPS   16            // channel groups per batch for kernel B
#define CH_PER   (NCH / GROUPS)   // 8
#define MAXDUP   256

// Scratch: winner map + duplicate lists (no dynamic allocation allowed)
__device__ int g_win[NBATCH * NCELLS];      // packed (y<<8)|tid, -1 = empty
__device__ int g_dupcnt[NBATCH];
__device__ int g_duplist[NBATCH * MAXDUP];  // packed (cell<<8)|tid

// ---------------- Kernel A: per-batch winner map (64 blocks) ----------------
__global__ __launch_bounds__(256)
void winner_kernel(const float* __restrict__ depth,      // (64,1,256)
                   const float* __restrict__ cam)        // (3,256)
{
    __shared__ __align__(16) int win[NCELLS];
    __shared__ int sdup;

    const int tid = threadIdx.x;        // 0..255 == point id
    const int b   = blockIdx.x;         // batch
    const int cl4 = tid * 4;

    // issue loads first
    const float d  = depth[b * NPTS + tid];
    const float cx = cam[          tid];
    const float cy = cam[  NPTS  + tid];
    const float cz = cam[2*NPTS  + tid];

    *reinterpret_cast<int4*>(&win[cl4]) = make_int4(-1, -1, -1, -1);
    if (tid == 0) sdup = 0;

    // ---- per-point voxel index math (bit-exact vs JAX float32) ----
    const float px = __fmul_rn(d, cx);
    const float py = __fadd_rn(__fmul_rn(d, cy), 1.72f);   // + CAM_HEIGHT
    const float pz = __fmul_rn(d, cz);

    const float CELLF = 0.1f;  // float32(3.2/32)
    const int xi = (int)floorf(__fdiv_rn(px, CELLF)) + (MAPS / 2);
    const int yi = (int)floorf(__fdiv_rn(py, CELLF));
    const int zi = (int)floorf(__fdiv_rn(pz, CELLF)) + MAPS;

    const bool valid = (xi >= 0) & (xi < MAPS) & (zi >= 0) & (zi < MAPS) & (yi < HMAXV);

    // replicate reference flat index semantics: flat = (z*32+x)*14 + y
    int cell = -1, ye = -1;
    if (valid) {
        const int vflat = (zi * MAPS + xi) * HMAXV + yi;
        if (vflat >= 0) {
            cell = vflat / HMAXV;           // ye in [0,13]
            ye   = vflat - cell * HMAXV;
        }
    }
    __syncthreads();   // init visible

    // phase 1: packed winner max (y major, tid minor)
    if (cell >= 0) atomicMax(&win[cell], (ye << 8) | tid);
    __syncthreads();

    // phase 2: losers tied at winning voxel register as duplicates (rare)
    int myslot = -1, myent = 0;
    if (cell >= 0) {
        const int w = win[cell];
        if ((w >> 8) == ye && (w & 255) != tid) {
            myslot = atomicAdd(&sdup, 1);
            myent  = (cell << 8) | tid;
        }
    }
    __syncthreads();

    // write results to global scratch (coalesced)
    *reinterpret_cast<int4*>(&g_win[b * NCELLS + cl4]) =
        *reinterpret_cast<const int4*>(&win[cl4]);
    if (myslot >= 0 && myslot < MAXDUP)
        g_duplist[b * MAXDUP + myslot] = myent;
    if (tid == 0)
        g_dupcnt[b] = sdup;
}

// ---------------- Kernel B: pure gather/stream epilogue (1024 blocks) ----------------
__global__ __launch_bounds__(256)
void stream_kernel(const float* __restrict__ features,   // (64,128,256)
                   float* __restrict__ out)              // (64,128,32,32)
{
    __shared__ __align__(16) float sf[CH_PER * NPTS];    // staged features (8KB)

    const int tid = threadIdx.x;
    const int b   = blockIdx.y;         // batch
    const int g   = blockIdx.x;         // channel group
    const int cl4 = tid * 4;

    // win slice for this thread's 4 cells (L2-hot, coalesced int4)
    const int4 w4 = *reinterpret_cast<const int4*>(&g_win[b * NCELLS + cl4]);
    const int ndup = g_dupcnt[b];       // uniform scalar load

    // stage features (coalesced LDG.128)
    const float* __restrict__ fb = features + (size_t)(b * NCH + g * CH_PER) * NPTS;
    {
        const float4* __restrict__ src = reinterpret_cast<const float4*>(fb);
        float4* dst = reinterpret_cast<float4*>(sf);
        #pragma unroll
        for (int i = 0; i < (CH_PER * NPTS / 4) / 256; i++)
            dst[tid + i * 256] = src[tid + i * 256];
    }

    const int f0 = (w4.x < 0) ? -1 : (w4.x & 255);
    const int f1 = (w4.y < 0) ? -1 : (w4.y & 255);
    const int f2 = (w4.z < 0) ? -1 : (w4.z & 255);
    const int f3 = (w4.w < 0) ? -1 : (w4.w & 255);

    // duplicate check (ndup is tiny; uniform-address LDGs, broadcast)
    bool hasdup = false;
    for (int k = 0; k < ndup; k++) {
        const int dc = g_duplist[b * MAXDUP + k] >> 8;
        hasdup |= (dc >= cl4) && (dc < cl4 + 4);
    }

    __syncthreads();   // single barrier: staging complete

    float* __restrict__ ob = out + (size_t)(b * NCH + g * CH_PER) * NCELLS + cl4;

    if (!hasdup) {
        // common path: predicated smem gathers + coalesced STG.128
        #pragma unroll
        for (int c = 0; c < CH_PER; c++) {
            const float* __restrict__ frow = sf + c * NPTS;
            float4 v = make_float4(0.f, 0.f, 0.f, 0.f);
            if (f0 >= 0) v.x = frow[f0];
            if (f1 >= 0) v.y = frow[f1];
            if (f2 >= 0) v.z = frow[f2];
            if (f3 >= 0) v.w = frow[f3];
            *reinterpret_cast<float4*>(ob + c * NCELLS) = v;
        }
    } else {
        // rare threads owning a duplicated cell: add loser contributions too
        #pragma unroll 4
        for (int c = 0; c < CH_PER; c++) {
            const float* __restrict__ frow = sf + c * NPTS;
            float4 v = make_float4(0.f, 0.f, 0.f, 0.f);
            if (f0 >= 0) v.x = frow[f0];
            if (f1 >= 0) v.y = frow[f1];
            if (f2 >= 0) v.z = frow[f2];
            if (f3 >= 0) v.w = frow[f3];
            for (int k = 0; k < ndup; k++) {
                const int e  = g_duplist[b * MAXDUP + k];
                const int dc = e >> 8;
                const int dt = e & 255;
                if      (dc == cl4    ) v.x += frow[dt];
                else if (dc == cl4 + 1) v.y += frow[dt];
                else if (dc == cl4 + 2) v.z += frow[dt];
                else if (dc == cl4 + 3) v.w += frow[dt];
            }
            *reinterpret_cast<float4*>(ob + c * NCELLS) = v;
        }
    }
}

extern "C" void kernel_launch(void* const* d_in, const int* in_sizes, int n_in,
                              void* d_out, int out_size)
{
    const float* features = (const float*)d_in[0];   // 64*128*16*16
    const float* depth    = (const float*)d_in[1];   // 64*1*16*16
    const float* cam      = (const float*)d_in[2];   // 3*256
    float*       out      = (float*)d_out;           // 64*128*32*32

    winner_kernel<<<NBATCH, 256>>>(depth, cam);
    dim3 grid(GROUPS, NBATCH);
    stream_kernel<<<grid, 256>>>(features, out);
}

// round 13
// speedup vs baseline: 1.2786x; 1.1663x over previous
#include <cuda_runtime.h>
#include <math.h>

// Problem constants
#define NBATCH   64
#define NCH      128
#define NPTS     256           // 16x16 image grid
#define MAPS     32            // BEV map size
#define NCELLS   (MAPS*MAPS)   // 1024
#define HMAXV    14
#define GROUPS   16            // channel groups per batch for kernel B
#define CH_PER   (NCH / GROUPS)   // 8
#define MAXEXTRA 256
#define NBMW     (NCELLS / 32)   // 32 bitmap words per batch

// Scratch (static __device__ globals — no dynamic allocation)
__device__ int      g_win[NBATCH * NCELLS];        // packed (y<<8)|tid, -1 = empty
__device__ unsigned g_bitmap[NBATCH * NBMW];       // per-cell "has extra contributor"
__device__ int      g_ecnt[NBATCH];
__device__ int      g_extras[NBATCH * MAXEXTRA];   // packed (cell<<8)|tid

// ---------------- Kernel A: per-batch winner map + extras (64 blocks) ----------------
__global__ __launch_bounds__(256)
void winner_kernel(const float* __restrict__ depth,      // (64,1,256)
                   const float* __restrict__ cam)        // (3,256)
{
    __shared__ __align__(16) int win[NCELLS];
    __shared__ unsigned sbm[NBMW];
    __shared__ int sdup;

    const int tid = threadIdx.x;        // 0..255 == point id
    const int b   = blockIdx.x;         // batch
    const int cl4 = tid * 4;

    // issue loads first
    const float d  = depth[b * NPTS + tid];
    const float cx = cam[          tid];
    const float cy = cam[  NPTS  + tid];
    const float cz = cam[2*NPTS  + tid];

    *reinterpret_cast<int4*>(&win[cl4]) = make_int4(-1, -1, -1, -1);
    if (tid < NBMW) sbm[tid] = 0u;
    if (tid == 0) sdup = 0;

    // ---- per-point voxel index math (bit-exact vs JAX float32) ----
    const float px = __fmul_rn(d, cx);
    const float py = __fadd_rn(__fmul_rn(d, cy), 1.72f);   // + CAM_HEIGHT
    const float pz = __fmul_rn(d, cz);

    const float CELLF = 0.1f;  // float32(3.2/32)
    const int xi = (int)floorf(__fdiv_rn(px, CELLF)) + (MAPS / 2);
    const int yi = (int)floorf(__fdiv_rn(py, CELLF));
    const int zi = (int)floorf(__fdiv_rn(pz, CELLF)) + MAPS;

    const bool valid = (xi >= 0) & (xi < MAPS) & (zi >= 0) & (zi < MAPS) & (yi < HMAXV);

    // replicate reference flat index semantics: flat = (z*32+x)*14 + y
    int cell = -1, ye = -1;
    if (valid) {
        const int vflat = (zi * MAPS + xi) * HMAXV + yi;
        if (vflat >= 0) {
            cell = vflat / HMAXV;           // ye in [0,13]
            ye   = vflat - cell * HMAXV;
        }
    }
    __syncthreads();   // init visible

    // phase 1: packed winner max (y major, tid minor)
    if (cell >= 0) atomicMax(&win[cell], (ye << 8) | tid);
    __syncthreads();

    // phase 2: losers tied at winning voxel -> extras list + bitmap bit (rare)
    int myslot = -1, myent = 0;
    if (cell >= 0) {
        const int w = win[cell];
        if ((w >> 8) == ye && (w & 255) != tid) {
            myslot = atomicAdd(&sdup, 1);
            myent  = (cell << 8) | tid;
            atomicOr(&sbm[cell >> 5], 1u << (cell & 31));
        }
    }
    __syncthreads();

    // write scratch (coalesced)
    *reinterpret_cast<int4*>(&g_win[b * NCELLS + cl4]) =
        *reinterpret_cast<const int4*>(&win[cl4]);
    if (tid < NBMW) g_bitmap[b * NBMW + tid] = sbm[tid];
    if (myslot >= 0 && myslot < MAXEXTRA)
        g_extras[b * MAXEXTRA + myslot] = myent;
    if (tid == 0) g_ecnt[b] = sdup;
}

// ---------------- Kernel B: pure gather/stream epilogue (1024 blocks) ----------------
__global__ __launch_bounds__(256)
void stream_kernel(const float* __restrict__ features,   // (64,128,256)
                   float* __restrict__ out)              // (64,128,32,32)
{
    __shared__ __align__(16) float sf[CH_PER * NPTS];    // staged features (8KB)

    const int tid = threadIdx.x;
    const int b   = blockIdx.y;         // batch
    const int g   = blockIdx.x;         // channel group
    const int cl4 = tid * 4;

    // --- issue all independent loads up front ---
    const int4 w4 = *reinterpret_cast<const int4*>(&g_win[b * NCELLS + cl4]);
    const unsigned bmw = g_bitmap[b * NBMW + (cl4 >> 5)];   // broadcast within warp

    const float* __restrict__ fb = features + (size_t)(b * NCH + g * CH_PER) * NPTS;
    {
        const float4* __restrict__ src = reinterpret_cast<const float4*>(fb);
        float4* dst = reinterpret_cast<float4*>(sf);
        #pragma unroll
        for (int i = 0; i < (CH_PER * NPTS / 4) / 256; i++)   // 2 iters
            dst[tid + i * 256] = src[tid + i * 256];
    }

    const int f0 = (w4.x < 0) ? -1 : (w4.x & 255);
    const int f1 = (w4.y < 0) ? -1 : (w4.y & 255);
    const int f2 = (w4.z < 0) ? -1 : (w4.z & 255);
    const int f3 = (w4.w < 0) ? -1 : (w4.w & 255);

    const bool hasextra = (bmw >> (cl4 & 31)) & 0xF;   // O(1) dup test

    __syncthreads();   // single barrier: staging complete

    float* __restrict__ ob = out + (size_t)(b * NCH + g * CH_PER) * NCELLS + cl4;

    if (!hasextra) {
        // common path: predicated smem gathers + coalesced STG.128
        #pragma unroll
        for (int c = 0; c < CH_PER; c++) {
            const float* __restrict__ frow = sf + c * NPTS;
            float4 v = make_float4(0.f, 0.f, 0.f, 0.f);
            if (f0 >= 0) v.x = frow[f0];
            if (f1 >= 0) v.y = frow[f1];
            if (f2 >= 0) v.z = frow[f2];
            if (f3 >= 0) v.w = frow[f3];
            *reinterpret_cast<float4*>(ob + c * NCELLS) = v;
        }
    } else {
        // rare threads owning a multi-contributor cell
        const int ne = g_ecnt[b];
        #pragma unroll 4
        for (int c = 0; c < CH_PER; c++) {
            const float* __restrict__ frow = sf + c * NPTS;
            float4 v = make_float4(0.f, 0.f, 0.f, 0.f);
            if (f0 >= 0) v.x = frow[f0];
            if (f1 >= 0) v.y = frow[f1];
            if (f2 >= 0) v.z = frow[f2];
            if (f3 >= 0) v.w = frow[f3];
            for (int k = 0; k < ne; k++) {
                const int e  = g_extras[b * MAXEXTRA + k];
                const int dc = e >> 8;
                const int dt = e & 255;
                if      (dc == cl4    ) v.x += frow[dt];
                else if (dc == cl4 + 1) v.y += frow[dt];
                else if (dc == cl4 + 2) v.z += frow[dt];
                else if (dc == cl4 + 3) v.w += frow[dt];
            }
            *reinterpret_cast<float4*>(ob + c * NCELLS) = v;
        }
    }
}

extern "C" void kernel_launch(void* const* d_in, const int* in_sizes, int n_in,
                              void* d_out, int out_size)
{
    const float* features = (const float*)d_in[0];   // 64*128*16*16
    const float* depth    = (const float*)d_in[1];   // 64*1*16*16
    const float* cam      = (const float*)d_in[2];   // 3*256
    float*       out      = (float*)d_out;           // 64*128*32*32

    winner_kernel<<<NBATCH, 256>>>(depth, cam);
    dim3 grid(GROUPS, NBATCH);
    stream_kernel<<<grid, 256>>>(features, out);
}